// round 12
// baseline (speedup 1.0000x reference)
#include <cuda_runtime.h>
#include <cuda_fp16.h>
#include <math.h>

#define N_NODES 30000
#define E_EDGES 480000
#define VDIM    512
#define HID     32

#define SCAN_BLK 512
#define NBLKS ((N_NODES + SCAN_BLK - 1) / SCAN_BLK)   // 59

// k_A interleaved roles: groups of 11 blocks = 10 vnorm + 1 aux
#define KA_GRID  4125      // 375 groups
#define HIST_BLKS 256
#define BN_BLKS   118
// k_B interleaved roles: groups of 17 = 16 fill + 1 mlp
#define FILL_BLKS 1875     // one edge per thread (1875*256 = 480000)
#define MLP_BLKS  118
#define KB_GRID   (118 * 17)   // 2006

// ---- scratch (__device__ globals; no allocation allowed) ----
__device__ __half g_vh[N_NODES * VDIM];    // normalized visual, fp16 (30.7 MB)
__device__ float  g_p[N_NODES];
__device__ int    g_cnt[N_NODES];
__device__ int    g_rowstart[N_NODES + 1];
__device__ int    g_cursor[N_NODES];
__device__ int    g_csr[E_EDGES];          // src indices grouped by dst
__device__ int    g_bsum[NBLKS];
__device__ int    g_arrive;
__device__ float  g_sum[HID];
__device__ float  g_sumsq[HID];
__device__ float  g_scale[HID];
__device__ float  g_shift[HID];
__device__ float  g_u[HID];
__device__ float  g_c;

// ---------------------------------------------------------------------------
__global__ void k_zero() {
    int i = blockIdx.x * blockDim.x + threadIdx.x;
    int stride = gridDim.x * blockDim.x;
    for (int j = i; j < N_NODES; j += stride) g_cnt[j] = 0;
    if (i < HID) { g_sum[i] = 0.f; g_sumsq[i] = 0.f; }
    if (i == HID) g_arrive = 0;
}

// ---------------------------------------------------------------------------
// K_A: interleaved  vnorm | hist | bnstats
// ---------------------------------------------------------------------------
__global__ void k_A(const float* __restrict__ visual,
                    const int* __restrict__ ei,
                    const float* __restrict__ x,
                    const float* __restrict__ w1,
                    const float* __restrict__ b1) {
    int b = blockIdx.x;
    int r = b % 11, q = b / 11;
    if (r < 10) {
        // ---- vnorm: warp per node ----
        int vb   = q * 10 + r;
        int gw   = (vb * blockDim.x + threadIdx.x) >> 5;
        int lane = threadIdx.x & 31;
        if (gw >= N_NODES) return;
        const float4* v = (const float4*)(visual + (size_t)gw * VDIM);
        float4 f[4];
        float s = 0.f;
#pragma unroll
        for (int i = 0; i < 4; i++) {
            f[i] = v[i * 32 + lane];
            s = fmaf(f[i].x, f[i].x, s); s = fmaf(f[i].y, f[i].y, s);
            s = fmaf(f[i].z, f[i].z, s); s = fmaf(f[i].w, f[i].w, s);
        }
#pragma unroll
        for (int off = 16; off > 0; off >>= 1) s += __shfl_xor_sync(0xffffffffu, s, off);
        float rn = 1.0f / fmaxf(sqrtf(s), 1e-8f);
        __half2* out = (__half2*)(g_vh + (size_t)gw * VDIM);
#pragma unroll
        for (int i = 0; i < 4; i++) {
            __half2 h0 = __floats2half2_rn(f[i].x * rn, f[i].y * rn);
            __half2 h1 = __floats2half2_rn(f[i].z * rn, f[i].w * rn);
            uint2 pk;
            pk.x = *(unsigned int*)&h0;
            pk.y = *(unsigned int*)&h1;
            *(uint2*)(out + i * 64 + lane * 2) = pk;
        }
    } else if (q < HIST_BLKS) {
        // ---- hist ----
        int i = q * blockDim.x + threadIdx.x;
        int stride = HIST_BLKS * blockDim.x;
        for (int e = i; e < E_EDGES; e += stride)
            atomicAdd(&g_cnt[ei[E_EDGES + e]], 1);
    } else if (q < HIST_BLKS + BN_BLKS) {
        // ---- bnstats ----
        int n = (q - HIST_BLKS) * blockDim.x + threadIdx.x;
        int lane = threadIdx.x & 31;
        bool valid = (n < N_NODES);
        float x0 = 0.f, x1 = 0.f;
        if (valid) { x0 = x[2 * n]; x1 = x[2 * n + 1]; }
#pragma unroll
        for (int k = 0; k < HID; k++) {
            float h = valid ? fmaf(w1[2 * k], x0, fmaf(w1[2 * k + 1], x1, b1[k])) : 0.f;
            float s = h, s2 = h * h;
#pragma unroll
            for (int off = 16; off > 0; off >>= 1) {
                s  += __shfl_xor_sync(0xffffffffu, s,  off);
                s2 += __shfl_xor_sync(0xffffffffu, s2, off);
            }
            if (lane == 0) {
                atomicAdd(&g_sum[k], s);
                atomicAdd(&g_sumsq[k], s2);
            }
        }
    }
}

// ---------------------------------------------------------------------------
// K_scanprep: blocks [0,59) grid-cooperative exclusive scan; block 59 = prep.
// ---------------------------------------------------------------------------
__global__ void k_scanprep(const float* __restrict__ gamma,
                           const float* __restrict__ beta,
                           const float* __restrict__ wc,
                           const float* __restrict__ bc,
                           const float* __restrict__ wp,
                           const float* __restrict__ bp) {
    int b = blockIdx.x;
    if (b == NBLKS) {
        int k = threadIdx.x;
        if (k >= HID) return;
        const float invN = 1.0f / (float)N_NODES;
        float mu  = g_sum[k] * invN;
        float var = g_sumsq[k] * invN - mu * mu;
        float rstd = rsqrtf(var + 1e-5f);
        float sc = rstd * gamma[k];
        g_scale[k] = sc;
        g_shift[k] = beta[k] - mu * sc;
        float u = 0.f;
#pragma unroll
        for (int j = 0; j < HID; j++) u = fmaf(wp[j], wc[j * HID + k], u);
        g_u[k] = u;
        if (k == 0) {
            float c = bp[0];
#pragma unroll
            for (int j = 0; j < HID; j++) c = fmaf(wp[j], bc[j], c);
            g_c = c;
        }
        return;
    }

    __shared__ int wsum[SCAN_BLK / 32 + 1];
    __shared__ int s_boff;
    int tid = threadIdx.x, lane = tid & 31, wid = tid >> 5;
    int i = b * SCAN_BLK + tid;
    int v = (i < N_NODES) ? g_cnt[i] : 0;
    int xv = v;
#pragma unroll
    for (int off = 1; off < 32; off <<= 1) {
        int y = __shfl_up_sync(0xffffffffu, xv, off);
        if (lane >= off) xv += y;
    }
    if (lane == 31) wsum[wid] = xv;
    __syncthreads();
    if (tid == 0) {
        int run = 0;
#pragma unroll
        for (int k = 0; k < SCAN_BLK / 32; k++) { int t = wsum[k]; wsum[k] = run; run += t; }
        g_bsum[b] = run;
        __threadfence();
        atomicAdd(&g_arrive, 1);
    }
    __syncthreads();
    int local_excl = xv - v + wsum[wid];

    if (tid == 0) {
        while (*(volatile int*)&g_arrive != NBLKS) { /* spin */ }
    }
    __syncthreads();
    __threadfence();

    if (wid == 0) {
        int a0 = (lane < b) ? g_bsum[lane] : 0;
        int a1 = (lane + 32 < b) ? g_bsum[lane + 32] : 0;
        int t = a0 + a1;
#pragma unroll
        for (int off = 16; off > 0; off >>= 1) t += __shfl_xor_sync(0xffffffffu, t, off);
        if (lane == 0) s_boff = t;
    }
    __syncthreads();

    if (i < N_NODES) {
        int rr = local_excl + s_boff;
        g_rowstart[i] = rr;
        g_cursor[i] = rr;
    }
    if (b == NBLKS - 1 && tid == 0) g_rowstart[N_NODES] = E_EDGES;
}

// ---------------------------------------------------------------------------
// K_B: interleaved  fill (one edge per thread) | mlp
// ---------------------------------------------------------------------------
__global__ void k_B(const int* __restrict__ ei,
                    const float* __restrict__ x,
                    const float* __restrict__ w1,
                    const float* __restrict__ b1,
                    const float* __restrict__ prelu_a,
                    const float* __restrict__ w2,
                    const float* __restrict__ b2) {
    __shared__ float swu[HID];
    __shared__ float ssc[HID], ssh[HID];
    __shared__ float sconst;
    int b = blockIdx.x;
    int r = b % 17, q = b / 17;
    if (r < 16) {
        int fb = q * 16 + r;
        if (fb >= FILL_BLKS) return;
        int e = fb * blockDim.x + threadIdx.x;   // one edge per thread
        int dst = ei[E_EDGES + e];
        int src = ei[e];
        int pos = atomicAdd(&g_cursor[dst], 1);
        g_csr[pos] = src;
    } else {
        if (threadIdx.x < HID) {
            int k = threadIdx.x;
            float wu = 0.f;
#pragma unroll
            for (int j = 0; j < HID; j++) wu = fmaf(g_u[j], w2[j * HID + k], wu);
            swu[k] = wu;
            ssc[k] = g_scale[k];
            ssh[k] = g_shift[k];
            if (k == 0) {
                float c2 = 0.f;
#pragma unroll
                for (int j = 0; j < HID; j++) c2 = fmaf(g_u[j], b2[j], c2);
                sconst = c2;
            }
        }
        __syncthreads();

        int n = q * blockDim.x + threadIdx.x;
        if (n >= N_NODES) return;
        float a = prelu_a[0];
        float x0 = x[2 * n], x1 = x[2 * n + 1];
        float p = sconst;
#pragma unroll
        for (int k = 0; k < HID; k++) {
            float h1 = fmaf(w1[2 * k], x0, fmaf(w1[2 * k + 1], x1, b1[k]));
            float h  = fmaf(h1, ssc[k], ssh[k]);
            float hp = (h >= 0.f) ? h : a * h;
            p = fmaf(hp, swu[k], p);
        }
        g_p[n] = p;
    }
}

// ---------------------------------------------------------------------------
// K_agg: BLOCK per dst node, 128 threads, thread owns 4 dims (one uint2).
// Edge metadata staged in smem by warp 0; src-row loads pipelined 2 deep.
// No output atomics: in-block reduction, single store per node.
// ---------------------------------------------------------------------------
__global__ void __launch_bounds__(128) k_agg(float* __restrict__ out) {
    __shared__ int   s_src[32];
    __shared__ float s_p[32];
    __shared__ float s_part[4];

    int node = blockIdx.x;
    int tid  = threadIdx.x;
    int lane = tid & 31;
    int wid  = tid >> 5;

    int beg = g_rowstart[node];
    int end = g_rowstart[node + 1];

    const uint2* vh2 = (const uint2*)g_vh;   // 128 uint2 per row

    float acc0 = 0.f, acc1 = 0.f, acc2 = 0.f, acc3 = 0.f;

    for (int base = beg; base < end; base += 32) {
        int cnt = min(32, end - base);
        __syncthreads();                      // protect smem reuse
        if (tid < cnt) {
            int s = __ldg(&g_csr[base + tid]);
            s_src[tid] = s;
            s_p[tid]   = __ldg(&g_p[s]);
        }
        __syncthreads();

        // 2-deep pipelined loop over the staged edges
        int   sj = s_src[0];
        float pj = s_p[0];
        uint2 av = vh2[(size_t)sj * 128 + tid];
        for (int j = 0; j < cnt; j++) {
            uint2 bv; float pn = 0.f;
            if (j + 1 < cnt) {
                int sn = s_src[j + 1];
                pn = s_p[j + 1];
                bv = vh2[(size_t)sn * 128 + tid];
            } else {
                bv = av;
            }
            float2 f0 = __half22float2(*(__half2*)&av.x);
            float2 f1 = __half22float2(*(__half2*)&av.y);
            acc0 = fmaf(f0.x, pj, acc0);
            acc1 = fmaf(f0.y, pj, acc1);
            acc2 = fmaf(f1.x, pj, acc2);
            acc3 = fmaf(f1.y, pj, acc3);
            av = bv; pj = pn;
        }
    }

    // dot with this thread's slice of the dst row
    uint2 dv = vh2[(size_t)node * 128 + tid];
    float2 g0 = __half22float2(*(__half2*)&dv.x);
    float2 g1 = __half22float2(*(__half2*)&dv.y);
    float s = acc0 * g0.x;
    s = fmaf(acc1, g0.y, s);
    s = fmaf(acc2, g1.x, s);
    s = fmaf(acc3, g1.y, s);

#pragma unroll
    for (int off = 16; off > 0; off >>= 1) s += __shfl_xor_sync(0xffffffffu, s, off);
    if (lane == 0) s_part[wid] = s;
    __syncthreads();
    if (tid == 0) {
        float tot = s_part[0] + s_part[1] + s_part[2] + s_part[3];
        float deg = (float)(end - beg);
        out[node] = tot / fmaxf(deg, 1.0f) + g_c;
    }
}

// ---------------------------------------------------------------------------
extern "C" void kernel_launch(void* const* d_in, const int* in_sizes, int n_in,
                              void* d_out, int out_size) {
    const float* x       = (const float*)d_in[0];
    const float* visual  = (const float*)d_in[1];
    const int*   ei      = (const int*)d_in[2];
    const float* w1      = (const float*)d_in[3];
    const float* b1      = (const float*)d_in[4];
    const float* gamma   = (const float*)d_in[5];
    const float* beta    = (const float*)d_in[6];
    const float* prelu_a = (const float*)d_in[7];
    const float* w2      = (const float*)d_in[8];
    const float* b2      = (const float*)d_in[9];
    const float* wc      = (const float*)d_in[10];
    const float* bc      = (const float*)d_in[11];
    const float* wp      = (const float*)d_in[12];
    const float* bp      = (const float*)d_in[13];
    float*       out     = (float*)d_out;

    k_zero<<<128, 256>>>();
    k_A<<<KA_GRID, 256>>>(visual, ei, x, w1, b1);
    k_scanprep<<<NBLKS + 1, SCAN_BLK>>>(gamma, beta, wc, bc, wp, bp);
    k_B<<<KB_GRID, 256>>>(ei, x, w1, b1, prelu_a, w2, b2);
    k_agg<<<N_NODES, 128>>>(out);
}

// round 13
// speedup vs baseline: 1.2056x; 1.2056x over previous
#include <cuda_runtime.h>
#include <cuda_fp16.h>
#include <math.h>

#define N_NODES 30000
#define E_EDGES 480000
#define VDIM    512
#define HID     32

#define SCAN_BLK 512
#define NBLKS ((N_NODES + SCAN_BLK - 1) / SCAN_BLK)   // 59

// k_A interleaved roles: groups of 11 blocks = 10 vnorm + 1 aux
#define KA_GRID  4125      // 375 groups
#define HIST_BLKS 256
#define BN_BLKS   118
// k_B interleaved roles: groups of 17 = 16 fill + 1 mlp
#define FILL_BLKS 1875     // one edge per thread (1875*256 = 480000)
#define MLP_BLKS  118
#define KB_GRID   (118 * 17)   // 2006

// ---- scratch (__device__ globals; no allocation allowed) ----
__device__ __half g_vh[N_NODES * VDIM];    // normalized visual, fp16 (30.7 MB)
__device__ float  g_p[N_NODES];
__device__ int    g_cnt[N_NODES];          // zeroed for next replay in k_B
__device__ int    g_rowstart[N_NODES + 1];
__device__ int    g_cursor[N_NODES];
__device__ int    g_csr[E_EDGES];          // src indices grouped by dst
__device__ int    g_bsum[NBLKS];
__device__ int    g_arrive;
__device__ float  g_sum[HID];
__device__ float  g_sumsq[HID];
__device__ float  g_scale[HID];
__device__ float  g_shift[HID];
__device__ float  g_u[HID];
__device__ float  g_c;

// ---------------------------------------------------------------------------
// K_A: interleaved  vnorm | hist | bnstats
// (g_cnt / g_sum / g_sumsq / g_arrive arrive zeroed: statics on call 1,
//  re-zeroed by k_B on every later call)
// ---------------------------------------------------------------------------
__global__ void k_A(const float* __restrict__ visual,
                    const int* __restrict__ ei,
                    const float* __restrict__ x,
                    const float* __restrict__ w1,
                    const float* __restrict__ b1) {
    int b = blockIdx.x;
    int r = b % 11, q = b / 11;
    if (r < 10) {
        // ---- vnorm: warp per node ----
        int vb   = q * 10 + r;
        int gw   = (vb * blockDim.x + threadIdx.x) >> 5;
        int lane = threadIdx.x & 31;
        if (gw >= N_NODES) return;
        const float4* v = (const float4*)(visual + (size_t)gw * VDIM);
        float4 f[4];
        float s = 0.f;
#pragma unroll
        for (int i = 0; i < 4; i++) {
            f[i] = v[i * 32 + lane];
            s = fmaf(f[i].x, f[i].x, s); s = fmaf(f[i].y, f[i].y, s);
            s = fmaf(f[i].z, f[i].z, s); s = fmaf(f[i].w, f[i].w, s);
        }
#pragma unroll
        for (int off = 16; off > 0; off >>= 1) s += __shfl_xor_sync(0xffffffffu, s, off);
        float rn = 1.0f / fmaxf(sqrtf(s), 1e-8f);
        __half2* out = (__half2*)(g_vh + (size_t)gw * VDIM);
#pragma unroll
        for (int i = 0; i < 4; i++) {
            __half2 h0 = __floats2half2_rn(f[i].x * rn, f[i].y * rn);
            __half2 h1 = __floats2half2_rn(f[i].z * rn, f[i].w * rn);
            uint2 pk;
            pk.x = *(unsigned int*)&h0;
            pk.y = *(unsigned int*)&h1;
            *(uint2*)(out + i * 64 + lane * 2) = pk;
        }
    } else if (q < HIST_BLKS) {
        // ---- hist ----
        int i = q * blockDim.x + threadIdx.x;
        int stride = HIST_BLKS * blockDim.x;
        for (int e = i; e < E_EDGES; e += stride)
            atomicAdd(&g_cnt[ei[E_EDGES + e]], 1);
    } else if (q < HIST_BLKS + BN_BLKS) {
        // ---- bnstats ----
        int n = (q - HIST_BLKS) * blockDim.x + threadIdx.x;
        int lane = threadIdx.x & 31;
        bool valid = (n < N_NODES);
        float x0 = 0.f, x1 = 0.f;
        if (valid) { x0 = x[2 * n]; x1 = x[2 * n + 1]; }
#pragma unroll
        for (int k = 0; k < HID; k++) {
            float h = valid ? fmaf(w1[2 * k], x0, fmaf(w1[2 * k + 1], x1, b1[k])) : 0.f;
            float s = h, s2 = h * h;
#pragma unroll
            for (int off = 16; off > 0; off >>= 1) {
                s  += __shfl_xor_sync(0xffffffffu, s,  off);
                s2 += __shfl_xor_sync(0xffffffffu, s2, off);
            }
            if (lane == 0) {
                atomicAdd(&g_sum[k], s);
                atomicAdd(&g_sumsq[k], s2);
            }
        }
    }
}

// ---------------------------------------------------------------------------
// K_scanprep: blocks [0,59) grid-cooperative exclusive scan; block 59 = prep.
// ---------------------------------------------------------------------------
__global__ void k_scanprep(const float* __restrict__ gamma,
                           const float* __restrict__ beta,
                           const float* __restrict__ wc,
                           const float* __restrict__ bc,
                           const float* __restrict__ wp,
                           const float* __restrict__ bp) {
    int b = blockIdx.x;
    if (b == NBLKS) {
        int k = threadIdx.x;
        if (k >= HID) return;
        const float invN = 1.0f / (float)N_NODES;
        float mu  = g_sum[k] * invN;
        float var = g_sumsq[k] * invN - mu * mu;
        float rstd = rsqrtf(var + 1e-5f);
        float sc = rstd * gamma[k];
        g_scale[k] = sc;
        g_shift[k] = beta[k] - mu * sc;
        float u = 0.f;
#pragma unroll
        for (int j = 0; j < HID; j++) u = fmaf(wp[j], wc[j * HID + k], u);
        g_u[k] = u;
        if (k == 0) {
            float c = bp[0];
#pragma unroll
            for (int j = 0; j < HID; j++) c = fmaf(wp[j], bc[j], c);
            g_c = c;
        }
        return;
    }

    __shared__ int wsum[SCAN_BLK / 32 + 1];
    __shared__ int s_boff;
    int tid = threadIdx.x, lane = tid & 31, wid = tid >> 5;
    int i = b * SCAN_BLK + tid;
    int v = (i < N_NODES) ? g_cnt[i] : 0;
    int xv = v;
#pragma unroll
    for (int off = 1; off < 32; off <<= 1) {
        int y = __shfl_up_sync(0xffffffffu, xv, off);
        if (lane >= off) xv += y;
    }
    if (lane == 31) wsum[wid] = xv;
    __syncthreads();
    if (tid == 0) {
        int run = 0;
#pragma unroll
        for (int k = 0; k < SCAN_BLK / 32; k++) { int t = wsum[k]; wsum[k] = run; run += t; }
        g_bsum[b] = run;
        __threadfence();
        atomicAdd(&g_arrive, 1);
    }
    __syncthreads();
    int local_excl = xv - v + wsum[wid];

    if (tid == 0) {
        while (*(volatile int*)&g_arrive != NBLKS) { /* spin */ }
    }
    __syncthreads();
    __threadfence();

    if (wid == 0) {
        int a0 = (lane < b) ? g_bsum[lane] : 0;
        int a1 = (lane + 32 < b) ? g_bsum[lane + 32] : 0;
        int t = a0 + a1;
#pragma unroll
        for (int off = 16; off > 0; off >>= 1) t += __shfl_xor_sync(0xffffffffu, t, off);
        if (lane == 0) s_boff = t;
    }
    __syncthreads();

    if (i < N_NODES) {
        int rr = local_excl + s_boff;
        g_rowstart[i] = rr;
        g_cursor[i] = rr;
    }
    if (b == NBLKS - 1 && tid == 0) g_rowstart[N_NODES] = E_EDGES;
}

// ---------------------------------------------------------------------------
// K_B: interleaved  fill (one edge per thread) | mlp (+ re-init for replay)
// ---------------------------------------------------------------------------
__global__ void k_B(const int* __restrict__ ei,
                    const float* __restrict__ x,
                    const float* __restrict__ w1,
                    const float* __restrict__ b1,
                    const float* __restrict__ prelu_a,
                    const float* __restrict__ w2,
                    const float* __restrict__ b2) {
    __shared__ float swu[HID];
    __shared__ float ssc[HID], ssh[HID];
    __shared__ float sconst;
    int b = blockIdx.x;
    int r = b % 17, q = b / 17;
    if (r < 16) {
        int fb = q * 16 + r;
        if (fb >= FILL_BLKS) return;
        int e = fb * blockDim.x + threadIdx.x;   // one edge per thread
        int dst = ei[E_EDGES + e];
        int src = ei[e];
        int pos = atomicAdd(&g_cursor[dst], 1);
        g_csr[pos] = src;
    } else {
        if (threadIdx.x < HID) {
            int k = threadIdx.x;
            float wu = 0.f;
#pragma unroll
            for (int j = 0; j < HID; j++) wu = fmaf(g_u[j], w2[j * HID + k], wu);
            swu[k] = wu;
            ssc[k] = g_scale[k];
            ssh[k] = g_shift[k];
            if (k == 0) {
                float c2 = 0.f;
#pragma unroll
                for (int j = 0; j < HID; j++) c2 = fmaf(g_u[j], b2[j], c2);
                sconst = c2;
            }
        }
        __syncthreads();

        // re-init consumed accumulators for the NEXT replay (consumers:
        // hist/bnstats feed scanprep, which has already run this launch)
        if (q == 0) {
            if (threadIdx.x < HID) { g_sum[threadIdx.x] = 0.f; g_sumsq[threadIdx.x] = 0.f; }
            if (threadIdx.x == HID) g_arrive = 0;
        }

        int n = q * blockDim.x + threadIdx.x;
        if (n >= N_NODES) return;
        g_cnt[n] = 0;                              // re-init for next replay
        float a = prelu_a[0];
        float x0 = x[2 * n], x1 = x[2 * n + 1];
        float p = sconst;
#pragma unroll
        for (int k = 0; k < HID; k++) {
            float h1 = fmaf(w1[2 * k], x0, fmaf(w1[2 * k + 1], x1, b1[k]));
            float h  = fmaf(h1, ssc[k], ssh[k]);
            float hp = (h >= 0.f) ? h : a * h;
            p = fmaf(hp, swu[k], p);
        }
        g_p[n] = p;
    }
}

// ---------------------------------------------------------------------------
// K_agg (R9 body, 64-thread blocks): warp per dst node; dst row preloaded;
// metadata gathered 32-wide; row loads software-pipelined 2 deep.
// ---------------------------------------------------------------------------
__global__ void __launch_bounds__(64) k_agg(float* __restrict__ out) {
    int gw   = (blockIdx.x * blockDim.x + threadIdx.x) >> 5;
    int lane = threadIdx.x & 31;
    if (gw >= N_NODES) return;

    int beg = g_rowstart[gw];
    int end = g_rowstart[gw + 1];

    const uint4* bptr = (const uint4*)(g_vh + (size_t)gw * VDIM);
    uint4 d0 = __ldg(bptr + lane);
    uint4 d1 = __ldg(bptr + 32 + lane);

    float acc[16];
#pragma unroll
    for (int j = 0; j < 16; j++) acc[j] = 0.f;

    for (int base = beg; base < end; base += 32) {
        int cnt = min(32, end - base);
        int   src = 0;
        float ps  = 0.f;
        if (lane < cnt) {
            src = __ldg(&g_csr[base + lane]);
            ps  = __ldg(&g_p[src]);
        }
        int   s0 = __shfl_sync(0xffffffffu, src, 0);
        float p0 = __shfl_sync(0xffffffffu, ps, 0);
        const uint4* r0 = (const uint4*)(g_vh + (size_t)s0 * VDIM);
        uint4 a0 = r0[lane];
        uint4 a1 = r0[32 + lane];

        for (int j = 0; j < cnt; j++) {
            uint4 b0, b1;
            float p1 = 0.f;
            if (j + 1 < cnt) {
                int s1 = __shfl_sync(0xffffffffu, src, j + 1);
                p1 = __shfl_sync(0xffffffffu, ps, j + 1);
                const uint4* rn = (const uint4*)(g_vh + (size_t)s1 * VDIM);
                b0 = rn[lane];
                b1 = rn[32 + lane];
            } else {
                b0 = a0; b1 = a1;
            }
            float2 f;
            f = __half22float2(*(__half2*)&a0.x); acc[0]  = fmaf(f.x, p0, acc[0]);  acc[1]  = fmaf(f.y, p0, acc[1]);
            f = __half22float2(*(__half2*)&a0.y); acc[2]  = fmaf(f.x, p0, acc[2]);  acc[3]  = fmaf(f.y, p0, acc[3]);
            f = __half22float2(*(__half2*)&a0.z); acc[4]  = fmaf(f.x, p0, acc[4]);  acc[5]  = fmaf(f.y, p0, acc[5]);
            f = __half22float2(*(__half2*)&a0.w); acc[6]  = fmaf(f.x, p0, acc[6]);  acc[7]  = fmaf(f.y, p0, acc[7]);
            f = __half22float2(*(__half2*)&a1.x); acc[8]  = fmaf(f.x, p0, acc[8]);  acc[9]  = fmaf(f.y, p0, acc[9]);
            f = __half22float2(*(__half2*)&a1.y); acc[10] = fmaf(f.x, p0, acc[10]); acc[11] = fmaf(f.y, p0, acc[11]);
            f = __half22float2(*(__half2*)&a1.z); acc[12] = fmaf(f.x, p0, acc[12]); acc[13] = fmaf(f.y, p0, acc[13]);
            f = __half22float2(*(__half2*)&a1.w); acc[14] = fmaf(f.x, p0, acc[14]); acc[15] = fmaf(f.y, p0, acc[15]);
            a0 = b0; a1 = b1; p0 = p1;
        }
    }

    float s = 0.f;
    float2 f;
    f = __half22float2(*(__half2*)&d0.x); s = fmaf(acc[0],  f.x, s); s = fmaf(acc[1],  f.y, s);
    f = __half22float2(*(__half2*)&d0.y); s = fmaf(acc[2],  f.x, s); s = fmaf(acc[3],  f.y, s);
    f = __half22float2(*(__half2*)&d0.z); s = fmaf(acc[4],  f.x, s); s = fmaf(acc[5],  f.y, s);
    f = __half22float2(*(__half2*)&d0.w); s = fmaf(acc[6],  f.x, s); s = fmaf(acc[7],  f.y, s);
    f = __half22float2(*(__half2*)&d1.x); s = fmaf(acc[8],  f.x, s); s = fmaf(acc[9],  f.y, s);
    f = __half22float2(*(__half2*)&d1.y); s = fmaf(acc[10], f.x, s); s = fmaf(acc[11], f.y, s);
    f = __half22float2(*(__half2*)&d1.z); s = fmaf(acc[12], f.x, s); s = fmaf(acc[13], f.y, s);
    f = __half22float2(*(__half2*)&d1.w); s = fmaf(acc[14], f.x, s); s = fmaf(acc[15], f.y, s);

#pragma unroll
    for (int off = 16; off > 0; off >>= 1) s += __shfl_xor_sync(0xffffffffu, s, off);

    if (lane == 0) {
        float deg = (float)(end - beg);
        out[gw] = s / fmaxf(deg, 1.0f) + g_c;
    }
}

// ---------------------------------------------------------------------------
extern "C" void kernel_launch(void* const* d_in, const int* in_sizes, int n_in,
                              void* d_out, int out_size) {
    const float* x       = (const float*)d_in[0];
    const float* visual  = (const float*)d_in[1];
    const int*   ei      = (const int*)d_in[2];
    const float* w1      = (const float*)d_in[3];
    const float* b1      = (const float*)d_in[4];
    const float* gamma   = (const float*)d_in[5];
    const float* beta    = (const float*)d_in[6];
    const float* prelu_a = (const float*)d_in[7];
    const float* w2      = (const float*)d_in[8];
    const float* b2      = (const float*)d_in[9];
    const float* wc      = (const float*)d_in[10];
    const float* bc      = (const float*)d_in[11];
    const float* wp      = (const float*)d_in[12];
    const float* bp      = (const float*)d_in[13];
    float*       out     = (float*)d_out;

    k_A<<<KA_GRID, 256>>>(visual, ei, x, w1, b1);
    k_scanprep<<<NBLKS + 1, SCAN_BLK>>>(gamma, beta, wc, bc, wp, bp);
    k_B<<<KB_GRID, 256>>>(ei, x, w1, b1, prelu_a, w2, b2);
    k_agg<<<(N_NODES * 32 + 63) / 64, 64>>>(out);
}

// round 14
// speedup vs baseline: 1.2350x; 1.0244x over previous
#include <cuda_runtime.h>
#include <cuda_fp16.h>
#include <math.h>

#define N_NODES 30000
#define E_EDGES 480000
#define VDIM    512
#define HID     32

#define SCAN_BLK 512
#define NBLKS ((N_NODES + SCAN_BLK - 1) / SCAN_BLK)   // 59

// k_A interleaved roles: groups of 11 blocks = 10 vnorm + 1 aux
#define KA_GRID  4125      // 375 groups
#define HIST_BLKS 256
#define BN_BLKS   118
// k_B interleaved roles: groups of 17 = 16 fill + 1 mlp
#define FILL_BLKS 1875     // one edge per thread (1875*256 = 480000)
#define MLP_BLKS  118
#define KB_GRID   (118 * 17)   // 2006

// ---- scratch (__device__ globals; no allocation allowed) ----
__device__ __half g_vh[N_NODES * VDIM];    // normalized visual, fp16 (30.7 MB)
__device__ float  g_p[N_NODES];
__device__ int    g_cnt[N_NODES];          // zeroed for next replay in k_B
__device__ int    g_rowstart[N_NODES + 1];
__device__ int    g_cursor[N_NODES];
__device__ int    g_csr[E_EDGES];          // src indices grouped by dst
__device__ int    g_bsum[NBLKS];
__device__ int    g_arrive;
__device__ float  g_sum[HID];
__device__ float  g_sumsq[HID];
__device__ float  g_scale[HID];
__device__ float  g_shift[HID];
__device__ float  g_u[HID];
__device__ float  g_c;

// ---------------------------------------------------------------------------
// K_A: interleaved  vnorm | hist | bnstats
// ---------------------------------------------------------------------------
__global__ void k_A(const float* __restrict__ visual,
                    const int* __restrict__ ei,
                    const float* __restrict__ x,
                    const float* __restrict__ w1,
                    const float* __restrict__ b1) {
    int b = blockIdx.x;
    int r = b % 11, q = b / 11;
    if (r < 10) {
        // ---- vnorm: warp per node ----
        int vb   = q * 10 + r;
        int gw   = (vb * blockDim.x + threadIdx.x) >> 5;
        int lane = threadIdx.x & 31;
        if (gw >= N_NODES) return;
        const float4* v = (const float4*)(visual + (size_t)gw * VDIM);
        float4 f[4];
        float s = 0.f;
#pragma unroll
        for (int i = 0; i < 4; i++) {
            f[i] = v[i * 32 + lane];
            s = fmaf(f[i].x, f[i].x, s); s = fmaf(f[i].y, f[i].y, s);
            s = fmaf(f[i].z, f[i].z, s); s = fmaf(f[i].w, f[i].w, s);
        }
#pragma unroll
        for (int off = 16; off > 0; off >>= 1) s += __shfl_xor_sync(0xffffffffu, s, off);
        float rn = 1.0f / fmaxf(sqrtf(s), 1e-8f);
        __half2* out = (__half2*)(g_vh + (size_t)gw * VDIM);
#pragma unroll
        for (int i = 0; i < 4; i++) {
            __half2 h0 = __floats2half2_rn(f[i].x * rn, f[i].y * rn);
            __half2 h1 = __floats2half2_rn(f[i].z * rn, f[i].w * rn);
            uint2 pk;
            pk.x = *(unsigned int*)&h0;
            pk.y = *(unsigned int*)&h1;
            *(uint2*)(out + i * 64 + lane * 2) = pk;
        }
    } else if (q < HIST_BLKS) {
        // ---- hist ----
        int i = q * blockDim.x + threadIdx.x;
        int stride = HIST_BLKS * blockDim.x;
        for (int e = i; e < E_EDGES; e += stride)
            atomicAdd(&g_cnt[ei[E_EDGES + e]], 1);
    } else if (q < HIST_BLKS + BN_BLKS) {
        // ---- bnstats ----
        int n = (q - HIST_BLKS) * blockDim.x + threadIdx.x;
        int lane = threadIdx.x & 31;
        bool valid = (n < N_NODES);
        float x0 = 0.f, x1 = 0.f;
        if (valid) { x0 = x[2 * n]; x1 = x[2 * n + 1]; }
#pragma unroll
        for (int k = 0; k < HID; k++) {
            float h = valid ? fmaf(w1[2 * k], x0, fmaf(w1[2 * k + 1], x1, b1[k])) : 0.f;
            float s = h, s2 = h * h;
#pragma unroll
            for (int off = 16; off > 0; off >>= 1) {
                s  += __shfl_xor_sync(0xffffffffu, s,  off);
                s2 += __shfl_xor_sync(0xffffffffu, s2, off);
            }
            if (lane == 0) {
                atomicAdd(&g_sum[k], s);
                atomicAdd(&g_sumsq[k], s2);
            }
        }
    }
}

// ---------------------------------------------------------------------------
// K_scanprep: blocks [0,59) grid-cooperative exclusive scan; block 59 = prep.
// ---------------------------------------------------------------------------
__global__ void k_scanprep(const float* __restrict__ gamma,
                           const float* __restrict__ beta,
                           const float* __restrict__ wc,
                           const float* __restrict__ bc,
                           const float* __restrict__ wp,
                           const float* __restrict__ bp) {
    int b = blockIdx.x;
    if (b == NBLKS) {
        int k = threadIdx.x;
        if (k >= HID) return;
        const float invN = 1.0f / (float)N_NODES;
        float mu  = g_sum[k] * invN;
        float var = g_sumsq[k] * invN - mu * mu;
        float rstd = rsqrtf(var + 1e-5f);
        float sc = rstd * gamma[k];
        g_scale[k] = sc;
        g_shift[k] = beta[k] - mu * sc;
        float u = 0.f;
#pragma unroll
        for (int j = 0; j < HID; j++) u = fmaf(wp[j], wc[j * HID + k], u);
        g_u[k] = u;
        if (k == 0) {
            float c = bp[0];
#pragma unroll
            for (int j = 0; j < HID; j++) c = fmaf(wp[j], bc[j], c);
            g_c = c;
        }
        return;
    }

    __shared__ int wsum[SCAN_BLK / 32 + 1];
    __shared__ int s_boff;
    int tid = threadIdx.x, lane = tid & 31, wid = tid >> 5;
    int i = b * SCAN_BLK + tid;
    int v = (i < N_NODES) ? g_cnt[i] : 0;
    int xv = v;
#pragma unroll
    for (int off = 1; off < 32; off <<= 1) {
        int y = __shfl_up_sync(0xffffffffu, xv, off);
        if (lane >= off) xv += y;
    }
    if (lane == 31) wsum[wid] = xv;
    __syncthreads();
    if (tid == 0) {
        int run = 0;
#pragma unroll
        for (int k = 0; k < SCAN_BLK / 32; k++) { int t = wsum[k]; wsum[k] = run; run += t; }
        g_bsum[b] = run;
        __threadfence();
        atomicAdd(&g_arrive, 1);
    }
    __syncthreads();
    int local_excl = xv - v + wsum[wid];

    if (tid == 0) {
        while (*(volatile int*)&g_arrive != NBLKS) { /* spin */ }
    }
    __syncthreads();
    __threadfence();

    if (wid == 0) {
        int a0 = (lane < b) ? g_bsum[lane] : 0;
        int a1 = (lane + 32 < b) ? g_bsum[lane + 32] : 0;
        int t = a0 + a1;
#pragma unroll
        for (int off = 16; off > 0; off >>= 1) t += __shfl_xor_sync(0xffffffffu, t, off);
        if (lane == 0) s_boff = t;
    }
    __syncthreads();

    if (i < N_NODES) {
        int rr = local_excl + s_boff;
        g_rowstart[i] = rr;
        g_cursor[i] = rr;
    }
    if (b == NBLKS - 1 && tid == 0) g_rowstart[N_NODES] = E_EDGES;
}

// ---------------------------------------------------------------------------
// K_B: interleaved  fill (one edge per thread) | mlp (+ re-init for replay)
// ---------------------------------------------------------------------------
__global__ void k_B(const int* __restrict__ ei,
                    const float* __restrict__ x,
                    const float* __restrict__ w1,
                    const float* __restrict__ b1,
                    const float* __restrict__ prelu_a,
                    const float* __restrict__ w2,
                    const float* __restrict__ b2) {
    __shared__ float swu[HID];
    __shared__ float ssc[HID], ssh[HID];
    __shared__ float sconst;
    int b = blockIdx.x;
    int r = b % 17, q = b / 17;
    if (r < 16) {
        int fb = q * 16 + r;
        if (fb >= FILL_BLKS) return;
        int e = fb * blockDim.x + threadIdx.x;   // one edge per thread
        int dst = ei[E_EDGES + e];
        int src = ei[e];
        int pos = atomicAdd(&g_cursor[dst], 1);
        g_csr[pos] = src;
    } else {
        if (threadIdx.x < HID) {
            int k = threadIdx.x;
            float wu = 0.f;
#pragma unroll
            for (int j = 0; j < HID; j++) wu = fmaf(g_u[j], w2[j * HID + k], wu);
            swu[k] = wu;
            ssc[k] = g_scale[k];
            ssh[k] = g_shift[k];
            if (k == 0) {
                float c2 = 0.f;
#pragma unroll
                for (int j = 0; j < HID; j++) c2 = fmaf(g_u[j], b2[j], c2);
                sconst = c2;
            }
        }
        __syncthreads();

        // re-init consumed accumulators for the NEXT replay
        if (q == 0) {
            if (threadIdx.x < HID) { g_sum[threadIdx.x] = 0.f; g_sumsq[threadIdx.x] = 0.f; }
            if (threadIdx.x == HID) g_arrive = 0;
        }

        int n = q * blockDim.x + threadIdx.x;
        if (n >= N_NODES) return;
        g_cnt[n] = 0;                              // re-init for next replay
        float a = prelu_a[0];
        float x0 = x[2 * n], x1 = x[2 * n + 1];
        float p = sconst;
#pragma unroll
        for (int k = 0; k < HID; k++) {
            float h1 = fmaf(w1[2 * k], x0, fmaf(w1[2 * k + 1], x1, b1[k]));
            float h  = fmaf(h1, ssc[k], ssh[k]);
            float hp = (h >= 0.f) ? h : a * h;
            p = fmaf(hp, swu[k], p);
        }
        g_p[n] = p;
    }
}

// ---------------------------------------------------------------------------
// K_agg: warp per dst node, 64-thread blocks. Dst row converted to float
// ONCE; per edge: partial dot (16 FMA) + scalar accumulate (1 FMA) — instead
// of 32-FMA vector accumulation. Exact float-sum reordering of the reference.
// ---------------------------------------------------------------------------
__global__ void __launch_bounds__(64) k_agg(float* __restrict__ out) {
    int gw   = (blockIdx.x * blockDim.x + threadIdx.x) >> 5;
    int lane = threadIdx.x & 31;
    if (gw >= N_NODES) return;

    int beg = g_rowstart[gw];
    int end = g_rowstart[gw + 1];

    // preload + convert dst row slice to float (once)
    const uint4* bptr = (const uint4*)(g_vh + (size_t)gw * VDIM);
    uint4 du0 = __ldg(bptr + lane);
    uint4 du1 = __ldg(bptr + 32 + lane);
    float d[16];
    {
        float2 f;
        f = __half22float2(*(__half2*)&du0.x); d[0]  = f.x; d[1]  = f.y;
        f = __half22float2(*(__half2*)&du0.y); d[2]  = f.x; d[3]  = f.y;
        f = __half22float2(*(__half2*)&du0.z); d[4]  = f.x; d[5]  = f.y;
        f = __half22float2(*(__half2*)&du0.w); d[6]  = f.x; d[7]  = f.y;
        f = __half22float2(*(__half2*)&du1.x); d[8]  = f.x; d[9]  = f.y;
        f = __half22float2(*(__half2*)&du1.y); d[10] = f.x; d[11] = f.y;
        f = __half22float2(*(__half2*)&du1.z); d[12] = f.x; d[13] = f.y;
        f = __half22float2(*(__half2*)&du1.w); d[14] = f.x; d[15] = f.y;
    }

    float acc = 0.f;

    for (int base = beg; base < end; base += 32) {
        int cnt = min(32, end - base);
        int   src = 0;
        float ps  = 0.f;
        if (lane < cnt) {
            src = __ldg(&g_csr[base + lane]);
            ps  = __ldg(&g_p[src]);
        }
        int   s0 = __shfl_sync(0xffffffffu, src, 0);
        float p0 = __shfl_sync(0xffffffffu, ps, 0);
        const uint4* r0 = (const uint4*)(g_vh + (size_t)s0 * VDIM);
        uint4 a0 = r0[lane];
        uint4 a1 = r0[32 + lane];

        for (int j = 0; j < cnt; j++) {
            uint4 b0, b1;
            float p1 = 0.f;
            if (j + 1 < cnt) {
                int s1 = __shfl_sync(0xffffffffu, src, j + 1);
                p1 = __shfl_sync(0xffffffffu, ps, j + 1);
                const uint4* rn = (const uint4*)(g_vh + (size_t)s1 * VDIM);
                b0 = rn[lane];
                b1 = rn[32 + lane];
            } else {
                b0 = a0; b1 = a1;
            }
            // partial dot of src slice with preconverted dst slice
            float2 f;
            float partial;
            f = __half22float2(*(__half2*)&a0.x); partial = f.x * d[0];
                                                  partial = fmaf(f.y, d[1],  partial);
            f = __half22float2(*(__half2*)&a0.y); partial = fmaf(f.x, d[2],  partial);
                                                  partial = fmaf(f.y, d[3],  partial);
            f = __half22float2(*(__half2*)&a0.z); partial = fmaf(f.x, d[4],  partial);
                                                  partial = fmaf(f.y, d[5],  partial);
            f = __half22float2(*(__half2*)&a0.w); partial = fmaf(f.x, d[6],  partial);
                                                  partial = fmaf(f.y, d[7],  partial);
            f = __half22float2(*(__half2*)&a1.x); partial = fmaf(f.x, d[8],  partial);
                                                  partial = fmaf(f.y, d[9],  partial);
            f = __half22float2(*(__half2*)&a1.y); partial = fmaf(f.x, d[10], partial);
                                                  partial = fmaf(f.y, d[11], partial);
            f = __half22float2(*(__half2*)&a1.z); partial = fmaf(f.x, d[12], partial);
                                                  partial = fmaf(f.y, d[13], partial);
            f = __half22float2(*(__half2*)&a1.w); partial = fmaf(f.x, d[14], partial);
                                                  partial = fmaf(f.y, d[15], partial);
            acc = fmaf(p0, partial, acc);
            a0 = b0; a1 = b1; p0 = p1;
        }
    }

#pragma unroll
    for (int off = 16; off > 0; off >>= 1) acc += __shfl_xor_sync(0xffffffffu, acc, off);

    if (lane == 0) {
        float deg = (float)(end - beg);
        out[gw] = acc / fmaxf(deg, 1.0f) + g_c;
    }
}

// ---------------------------------------------------------------------------
extern "C" void kernel_launch(void* const* d_in, const int* in_sizes, int n_in,
                              void* d_out, int out_size) {
    const float* x       = (const float*)d_in[0];
    const float* visual  = (const float*)d_in[1];
    const int*   ei      = (const int*)d_in[2];
    const float* w1      = (const float*)d_in[3];
    const float* b1      = (const float*)d_in[4];
    const float* gamma   = (const float*)d_in[5];
    const float* beta    = (const float*)d_in[6];
    const float* prelu_a = (const float*)d_in[7];
    const float* w2      = (const float*)d_in[8];
    const float* b2      = (const float*)d_in[9];
    const float* wc      = (const float*)d_in[10];
    const float* bc      = (const float*)d_in[11];
    const float* wp      = (const float*)d_in[12];
    const float* bp      = (const float*)d_in[13];
    float*       out     = (float*)d_out;

    k_A<<<KA_GRID, 256>>>(visual, ei, x, w1, b1);
    k_scanprep<<<NBLKS + 1, SCAN_BLK>>>(gamma, beta, wc, bc, wp, bp);
    k_B<<<KB_GRID, 256>>>(ei, x, w1, b1, prelu_a, w2, b2);
    k_agg<<<(N_NODES * 32 + 63) / 64, 64>>>(out);
}

// round 15
// speedup vs baseline: 1.2834x; 1.0392x over previous
#include <cuda_runtime.h>
#include <cuda_fp16.h>
#include <math.h>

#define N_NODES 30000
#define E_EDGES 480000
#define VDIM    512
#define HID     32

#define SCAN_BLK 512
#define NBLKS ((N_NODES + SCAN_BLK - 1) / SCAN_BLK)   // 59

// k_A interleaved roles: groups of 11 blocks = 10 vnorm + 1 aux
#define KA_GRID  4125      // 375 groups
#define HIST_BLKS 256
#define BN_BLKS   118
// k_B interleaved roles: groups of 17 = 16 fill + 1 mlp
#define FILL_BLKS 1875     // one edge per thread (1875*256 = 480000)
#define MLP_BLKS  118
#define KB_GRID   (118 * 17)   // 2006

typedef unsigned long long ull;

// packed f32x2 helpers (sm_103a FFMA2 path — only reachable via PTX)
__device__ __forceinline__ ull pack2(float2 f) {
    ull r; asm("mov.b64 %0, {%1, %2};" : "=l"(r) : "f"(f.x), "f"(f.y)); return r;
}
__device__ __forceinline__ float2 unpack2(ull v) {
    float2 f; asm("mov.b64 {%0, %1}, %2;" : "=f"(f.x), "=f"(f.y) : "l"(v)); return f;
}
#define FMUL2(d, a, b)    asm("mul.rn.f32x2 %0, %1, %2;"     : "=l"(d) : "l"(a), "l"(b))
#define FFMA2(d, a, b, c) asm("fma.rn.f32x2 %0, %1, %2, %3;" : "=l"(d) : "l"(a), "l"(b), "l"(c))
#define FADD2(d, a, b)    asm("add.rn.f32x2 %0, %1, %2;"     : "=l"(d) : "l"(a), "l"(b))

// ---- scratch (__device__ globals; no allocation allowed) ----
__device__ __half g_vh[N_NODES * VDIM];    // normalized visual, fp16 (30.7 MB)
__device__ float  g_p[N_NODES];
__device__ int    g_cnt[N_NODES];          // zeroed for next replay in k_B
__device__ int    g_rowstart[N_NODES + 1];
__device__ int    g_cursor[N_NODES];
__device__ int    g_csr[E_EDGES];          // src indices grouped by dst
__device__ int    g_bsum[NBLKS];
__device__ int    g_arrive;
__device__ float  g_sum[HID];
__device__ float  g_sumsq[HID];
__device__ float  g_scale[HID];
__device__ float  g_shift[HID];
__device__ float  g_u[HID];
__device__ float  g_c;

// ---------------------------------------------------------------------------
// K_A: interleaved  vnorm | hist | bnstats
// ---------------------------------------------------------------------------
__global__ void k_A(const float* __restrict__ visual,
                    const int* __restrict__ ei,
                    const float* __restrict__ x,
                    const float* __restrict__ w1,
                    const float* __restrict__ b1) {
    int b = blockIdx.x;
    int r = b % 11, q = b / 11;
    if (r < 10) {
        // ---- vnorm: warp per node ----
        int vb   = q * 10 + r;
        int gw   = (vb * blockDim.x + threadIdx.x) >> 5;
        int lane = threadIdx.x & 31;
        if (gw >= N_NODES) return;
        const float4* v = (const float4*)(visual + (size_t)gw * VDIM);
        float4 f[4];
        float s = 0.f;
#pragma unroll
        for (int i = 0; i < 4; i++) {
            f[i] = v[i * 32 + lane];
            s = fmaf(f[i].x, f[i].x, s); s = fmaf(f[i].y, f[i].y, s);
            s = fmaf(f[i].z, f[i].z, s); s = fmaf(f[i].w, f[i].w, s);
        }
#pragma unroll
        for (int off = 16; off > 0; off >>= 1) s += __shfl_xor_sync(0xffffffffu, s, off);
        float rn = 1.0f / fmaxf(sqrtf(s), 1e-8f);
        __half2* out = (__half2*)(g_vh + (size_t)gw * VDIM);
#pragma unroll
        for (int i = 0; i < 4; i++) {
            __half2 h0 = __floats2half2_rn(f[i].x * rn, f[i].y * rn);
            __half2 h1 = __floats2half2_rn(f[i].z * rn, f[i].w * rn);
            uint2 pk;
            pk.x = *(unsigned int*)&h0;
            pk.y = *(unsigned int*)&h1;
            *(uint2*)(out + i * 64 + lane * 2) = pk;
        }
    } else if (q < HIST_BLKS) {
        // ---- hist ----
        int i = q * blockDim.x + threadIdx.x;
        int stride = HIST_BLKS * blockDim.x;
        for (int e = i; e < E_EDGES; e += stride)
            atomicAdd(&g_cnt[ei[E_EDGES + e]], 1);
    } else if (q < HIST_BLKS + BN_BLKS) {
        // ---- bnstats ----
        int n = (q - HIST_BLKS) * blockDim.x + threadIdx.x;
        int lane = threadIdx.x & 31;
        bool valid = (n < N_NODES);
        float x0 = 0.f, x1 = 0.f;
        if (valid) { x0 = x[2 * n]; x1 = x[2 * n + 1]; }
#pragma unroll
        for (int k = 0; k < HID; k++) {
            float h = valid ? fmaf(w1[2 * k], x0, fmaf(w1[2 * k + 1], x1, b1[k])) : 0.f;
            float s = h, s2 = h * h;
#pragma unroll
            for (int off = 16; off > 0; off >>= 1) {
                s  += __shfl_xor_sync(0xffffffffu, s,  off);
                s2 += __shfl_xor_sync(0xffffffffu, s2, off);
            }
            if (lane == 0) {
                atomicAdd(&g_sum[k], s);
                atomicAdd(&g_sumsq[k], s2);
            }
        }
    }
}

// ---------------------------------------------------------------------------
// K_scanprep: blocks [0,59) grid-cooperative exclusive scan; block 59 = prep.
// ---------------------------------------------------------------------------
__global__ void k_scanprep(const float* __restrict__ gamma,
                           const float* __restrict__ beta,
                           const float* __restrict__ wc,
                           const float* __restrict__ bc,
                           const float* __restrict__ wp,
                           const float* __restrict__ bp) {
    int b = blockIdx.x;
    if (b == NBLKS) {
        int k = threadIdx.x;
        if (k >= HID) return;
        const float invN = 1.0f / (float)N_NODES;
        float mu  = g_sum[k] * invN;
        float var = g_sumsq[k] * invN - mu * mu;
        float rstd = rsqrtf(var + 1e-5f);
        float sc = rstd * gamma[k];
        g_scale[k] = sc;
        g_shift[k] = beta[k] - mu * sc;
        float u = 0.f;
#pragma unroll
        for (int j = 0; j < HID; j++) u = fmaf(wp[j], wc[j * HID + k], u);
        g_u[k] = u;
        if (k == 0) {
            float c = bp[0];
#pragma unroll
            for (int j = 0; j < HID; j++) c = fmaf(wp[j], bc[j], c);
            g_c = c;
        }
        return;
    }

    __shared__ int wsum[SCAN_BLK / 32 + 1];
    __shared__ int s_boff;
    int tid = threadIdx.x, lane = tid & 31, wid = tid >> 5;
    int i = b * SCAN_BLK + tid;
    int v = (i < N_NODES) ? g_cnt[i] : 0;
    int xv = v;
#pragma unroll
    for (int off = 1; off < 32; off <<= 1) {
        int y = __shfl_up_sync(0xffffffffu, xv, off);
        if (lane >= off) xv += y;
    }
    if (lane == 31) wsum[wid] = xv;
    __syncthreads();
    if (tid == 0) {
        int run = 0;
#pragma unroll
        for (int k = 0; k < SCAN_BLK / 32; k++) { int t = wsum[k]; wsum[k] = run; run += t; }
        g_bsum[b] = run;
        __threadfence();
        atomicAdd(&g_arrive, 1);
    }
    __syncthreads();
    int local_excl = xv - v + wsum[wid];

    if (tid == 0) {
        while (*(volatile int*)&g_arrive != NBLKS) { /* spin */ }
    }
    __syncthreads();
    __threadfence();

    if (wid == 0) {
        int a0 = (lane < b) ? g_bsum[lane] : 0;
        int a1 = (lane + 32 < b) ? g_bsum[lane + 32] : 0;
        int t = a0 + a1;
#pragma unroll
        for (int off = 16; off > 0; off >>= 1) t += __shfl_xor_sync(0xffffffffu, t, off);
        if (lane == 0) s_boff = t;
    }
    __syncthreads();

    if (i < N_NODES) {
        int rr = local_excl + s_boff;
        g_rowstart[i] = rr;
        g_cursor[i] = rr;
    }
    if (b == NBLKS - 1 && tid == 0) g_rowstart[N_NODES] = E_EDGES;
}

// ---------------------------------------------------------------------------
// K_B: interleaved  fill (one edge per thread) | mlp (+ re-init for replay)
// ---------------------------------------------------------------------------
__global__ void k_B(const int* __restrict__ ei,
                    const float* __restrict__ x,
                    const float* __restrict__ w1,
                    const float* __restrict__ b1,
                    const float* __restrict__ prelu_a,
                    const float* __restrict__ w2,
                    const float* __restrict__ b2) {
    __shared__ float swu[HID];
    __shared__ float ssc[HID], ssh[HID];
    __shared__ float sconst;
    int b = blockIdx.x;
    int r = b % 17, q = b / 17;
    if (r < 16) {
        int fb = q * 16 + r;
        if (fb >= FILL_BLKS) return;
        int e = fb * blockDim.x + threadIdx.x;   // one edge per thread
        int dst = ei[E_EDGES + e];
        int src = ei[e];
        int pos = atomicAdd(&g_cursor[dst], 1);
        g_csr[pos] = src;
    } else {
        if (threadIdx.x < HID) {
            int k = threadIdx.x;
            float wu = 0.f;
#pragma unroll
            for (int j = 0; j < HID; j++) wu = fmaf(g_u[j], w2[j * HID + k], wu);
            swu[k] = wu;
            ssc[k] = g_scale[k];
            ssh[k] = g_shift[k];
            if (k == 0) {
                float c2 = 0.f;
#pragma unroll
                for (int j = 0; j < HID; j++) c2 = fmaf(g_u[j], b2[j], c2);
                sconst = c2;
            }
        }
        __syncthreads();

        // re-init consumed accumulators for the NEXT replay
        if (q == 0) {
            if (threadIdx.x < HID) { g_sum[threadIdx.x] = 0.f; g_sumsq[threadIdx.x] = 0.f; }
            if (threadIdx.x == HID) g_arrive = 0;
        }

        int n = q * blockDim.x + threadIdx.x;
        if (n >= N_NODES) return;
        g_cnt[n] = 0;                              // re-init for next replay
        float a = prelu_a[0];
        float x0 = x[2 * n], x1 = x[2 * n + 1];
        float p = sconst;
#pragma unroll
        for (int k = 0; k < HID; k++) {
            float h1 = fmaf(w1[2 * k], x0, fmaf(w1[2 * k + 1], x1, b1[k]));
            float h  = fmaf(h1, ssc[k], ssh[k]);
            float hp = (h >= 0.f) ? h : a * h;
            p = fmaf(hp, swu[k], p);
        }
        g_p[n] = p;
    }
}

// ---------------------------------------------------------------------------
// K_agg: warp per dst node, 64-thread blocks.
//  - dst slice pre-converted + packed into 8 f32x2 registers (once)
//  - per edge: 8 packed FFMA2 in 2 independent chains (vs 16 scalar FMA)
//  - branchless clamped prefetch (no per-edge divergence constructs)
//  - byte offsets shuffled instead of indices (no per-edge IMAD.WIDE)
// ---------------------------------------------------------------------------
__global__ void __launch_bounds__(64) k_agg(float* __restrict__ out) {
    int gw   = (blockIdx.x * blockDim.x + threadIdx.x) >> 5;
    int lane = threadIdx.x & 31;
    if (gw >= N_NODES) return;

    int beg = g_rowstart[gw];
    int end = g_rowstart[gw + 1];

    const char* vb0 = (const char*)g_vh + lane * 16;   // lane's first 16B slot
    const char* vb1 = vb0 + 512;                       // lane's second 16B slot

    // preload + convert + pack dst slice (once per node)
    uint4 du0 = __ldg((const uint4*)(vb0 + ((size_t)gw << 10)));
    uint4 du1 = __ldg((const uint4*)(vb1 + ((size_t)gw << 10)));
    ull D[8];
    D[0] = pack2(__half22float2(*(__half2*)&du0.x));
    D[1] = pack2(__half22float2(*(__half2*)&du0.y));
    D[2] = pack2(__half22float2(*(__half2*)&du0.z));
    D[3] = pack2(__half22float2(*(__half2*)&du0.w));
    D[4] = pack2(__half22float2(*(__half2*)&du1.x));
    D[5] = pack2(__half22float2(*(__half2*)&du1.y));
    D[6] = pack2(__half22float2(*(__half2*)&du1.z));
    D[7] = pack2(__half22float2(*(__half2*)&du1.w));

    float acc = 0.f;

    for (int base = beg; base < end; base += 32) {
        int cnt = min(32, end - base);
        int   off = 0;
        float ps  = 0.f;
        if (lane < cnt) {
            int s = __ldg(&g_csr[base + lane]);
            off = s << 10;                 // byte offset of row (1024 B/row)
            ps  = __ldg(&g_p[s]);
        }
        int   o0 = __shfl_sync(0xffffffffu, off, 0);
        float p0 = __shfl_sync(0xffffffffu, ps, 0);
        uint4 a0 = *(const uint4*)(vb0 + o0);
        uint4 a1 = *(const uint4*)(vb1 + o0);

        for (int j = 0; j < cnt; j++) {
            int jn = (j + 1 < cnt) ? (j + 1) : j;     // clamped (branchless)
            int   o1 = __shfl_sync(0xffffffffu, off, jn);
            float p1 = __shfl_sync(0xffffffffu, ps, jn);
            uint4 b0 = *(const uint4*)(vb0 + o1);
            uint4 b1 = *(const uint4*)(vb1 + o1);

            ull sv, cA, cB, cT;
            sv = pack2(__half22float2(*(__half2*)&a0.x)); FMUL2(cA, sv, D[0]);
            sv = pack2(__half22float2(*(__half2*)&a0.y)); FMUL2(cB, sv, D[1]);
            sv = pack2(__half22float2(*(__half2*)&a0.z)); FFMA2(cA, sv, D[2], cA);
            sv = pack2(__half22float2(*(__half2*)&a0.w)); FFMA2(cB, sv, D[3], cB);
            sv = pack2(__half22float2(*(__half2*)&a1.x)); FFMA2(cA, sv, D[4], cA);
            sv = pack2(__half22float2(*(__half2*)&a1.y)); FFMA2(cB, sv, D[5], cB);
            sv = pack2(__half22float2(*(__half2*)&a1.z)); FFMA2(cA, sv, D[6], cA);
            sv = pack2(__half22float2(*(__half2*)&a1.w)); FFMA2(cB, sv, D[7], cB);
            FADD2(cT, cA, cB);
            float2 t = unpack2(cT);
            acc = fmaf(p0, t.x + t.y, acc);

            a0 = b0; a1 = b1; p0 = p1;
        }
    }

#pragma unroll
    for (int off = 16; off > 0; off >>= 1) acc += __shfl_xor_sync(0xffffffffu, acc, off);

    if (lane == 0) {
        float deg = (float)(end - beg);
        out[gw] = acc / fmaxf(deg, 1.0f) + g_c;
    }
}

// ---------------------------------------------------------------------------
extern "C" void kernel_launch(void* const* d_in, const int* in_sizes, int n_in,
                              void* d_out, int out_size) {
    const float* x       = (const float*)d_in[0];
    const float* visual  = (const float*)d_in[1];
    const int*   ei      = (const int*)d_in[2];
    const float* w1      = (const float*)d_in[3];
    const float* b1      = (const float*)d_in[4];
    const float* gamma   = (const float*)d_in[5];
    const float* beta    = (const float*)d_in[6];
    const float* prelu_a = (const float*)d_in[7];
    const float* w2      = (const float*)d_in[8];
    const float* b2      = (const float*)d_in[9];
    const float* wc      = (const float*)d_in[10];
    const float* bc      = (const float*)d_in[11];
    const float* wp      = (const float*)d_in[12];
    const float* bp      = (const float*)d_in[13];
    float*       out     = (float*)d_out;

    k_A<<<KA_GRID, 256>>>(visual, ei, x, w1, b1);
    k_scanprep<<<NBLKS + 1, SCAN_BLK>>>(gamma, beta, wc, bc, wp, bp);
    k_B<<<KB_GRID, 256>>>(ei, x, w1, b1, prelu_a, w2, b2);
    k_agg<<<(N_NODES * 32 + 63) / 64, 64>>>(out);
}